// round 1
// baseline (speedup 1.0000x reference)
#include <cuda_runtime.h>
#include <math.h>

// ---------------------------------------------------------------------------
// Problem constants
// ---------------------------------------------------------------------------
constexpr int cB  = 32;
constexpr int cH  = 56;
constexpr int cW  = 56;
constexpr int cC  = 192;
constexpr int cWS = 7;
constexpr int cSS = 3;
constexpr int cNH = 6;
constexpr int cHD = 32;
constexpr int cN  = 49;          // tokens per window
constexpr int cNW = 64;          // windows per image
constexpr int ROWS = cB * cNW * cN;   // 100352
constexpr float SCALE = 0.17677669529663687f; // 32^-0.5

// ---------------------------------------------------------------------------
// Scratch (device globals -- no runtime allocation allowed)
// ---------------------------------------------------------------------------
__device__ float g_buf_a[(size_t)ROWS * cC];        //  77 MB
__device__ float g_buf_b[(size_t)ROWS * cC];        //  77 MB
__device__ float g_buf_big[(size_t)ROWS * 4 * cC];  // 308 MB (qkv 576 cols, then mlp 768 cols)

// ---------------------------------------------------------------------------
// LayerNorm (+ optional cyclic-shift + window-partition gather)
// blockDim = 192, one block per output row
// ---------------------------------------------------------------------------
template <bool SHIFT>
__global__ __launch_bounds__(192) void ln_kernel(
    const float* __restrict__ in, const float* __restrict__ g,
    const float* __restrict__ bb, float* __restrict__ out)
{
    const int r = blockIdx.x;
    size_t src;
    if (SHIFT) {
        int win = r / cN, n = r % cN;
        int b = win >> 6, wrem = win & 63;
        int wh = wrem >> 3, ww = wrem & 7;
        int ii = n / 7, jj = n % 7;
        int h = wh * 7 + ii + cSS; if (h >= cH) h -= cH;
        int w = ww * 7 + jj + cSS; if (w >= cW) w -= cW;
        src = (size_t)b * (cH * cW) + h * cW + w;
    } else {
        src = (size_t)r;
    }
    const int t = threadIdx.x;
    float v = in[src * cC + t];
    float s1 = v, s2 = v * v;
    #pragma unroll
    for (int o = 16; o; o >>= 1) {
        s1 += __shfl_xor_sync(0xffffffffu, s1, o);
        s2 += __shfl_xor_sync(0xffffffffu, s2, o);
    }
    __shared__ float sh1[6], sh2[6];
    const int wid = t >> 5, lane = t & 31;
    if (lane == 0) { sh1[wid] = s1; sh2[wid] = s2; }
    __syncthreads();
    float t1 = 0.f, t2 = 0.f;
    #pragma unroll
    for (int i = 0; i < 6; i++) { t1 += sh1[i]; t2 += sh2[i]; }
    const float mu  = t1 * (1.0f / cC);
    const float var = t2 * (1.0f / cC) - mu * mu;
    const float inv = rsqrtf(var + 1e-5f);
    out[(size_t)r * cC + t] = (v - mu) * inv * g[t] + bb[t];
}

// ---------------------------------------------------------------------------
// SGEMM: C[M,N] = A[M,K] @ B[K,N] (+ bias) (+ epilogue)
//   EPI 0: + bias                              (qkv)
//   EPI 1: gelu(+bias)                         (fc1)
//   EPI 2: scatter(window reverse + unshift) + residual(res)   (proj)
//   EPI 3: + bias + res[row,col]               (fc2, writes d_out)
// BM=128 BN=64 BK=8, 256 threads, 8x4 per-thread tile. Shapes divide exactly.
// ---------------------------------------------------------------------------
template <int EPI>
__global__ __launch_bounds__(256) void sgemm_kernel(
    const float* __restrict__ A, const float* __restrict__ Bm,
    const float* __restrict__ bias, const float* __restrict__ res,
    float* __restrict__ Cout, int Nn, int K)
{
    __shared__ float As[8][128];
    __shared__ float Bs[8][64];

    const int tid = threadIdx.x;
    const int ty = tid >> 4, tx = tid & 15;       // ty: 8-row group, tx: 4-col group
    const int rowBase = blockIdx.y * 128;
    const int colBase = blockIdx.x * 64;

    const int arow = tid >> 1;            // 0..127
    const int acol = (tid & 1) * 4;       // 0 or 4
    const int brow = tid >> 5;            // 0..7
    const int bcol = (tid & 31) * 2;      // 0..62

    float acc[8][4];
    #pragma unroll
    for (int i = 0; i < 8; i++)
        #pragma unroll
        for (int j = 0; j < 4; j++) acc[i][j] = 0.f;

    for (int k0 = 0; k0 < K; k0 += 8) {
        float4 av = *(const float4*)(A + (size_t)(rowBase + arow) * K + k0 + acol);
        float2 bv = *(const float2*)(Bm + (size_t)(k0 + brow) * Nn + colBase + bcol);
        __syncthreads();
        As[acol + 0][arow] = av.x;
        As[acol + 1][arow] = av.y;
        As[acol + 2][arow] = av.z;
        As[acol + 3][arow] = av.w;
        Bs[brow][bcol]     = bv.x;
        Bs[brow][bcol + 1] = bv.y;
        __syncthreads();
        #pragma unroll
        for (int kk = 0; kk < 8; kk++) {
            float a[8], b[4];
            #pragma unroll
            for (int i = 0; i < 8; i++) a[i] = As[kk][ty * 8 + i];
            #pragma unroll
            for (int j = 0; j < 4; j++) b[j] = Bs[kk][tx * 4 + j];
            #pragma unroll
            for (int i = 0; i < 8; i++)
                #pragma unroll
                for (int j = 0; j < 4; j++)
                    acc[i][j] += a[i] * b[j];
        }
    }

    #pragma unroll
    for (int i = 0; i < 8; i++) {
        const int r = rowBase + ty * 8 + i;
        size_t orow = (size_t)r;
        if (EPI == 2) {
            // window reverse + unshift scatter
            int win = r / cN, n = r % cN;
            int b = win >> 6, wrem = win & 63;
            int wh = wrem >> 3, ww = wrem & 7;
            int ii = n / 7, jj = n % 7;
            int h = wh * 7 + ii + cSS; if (h >= cH) h -= cH;
            int w = ww * 7 + jj + cSS; if (w >= cW) w -= cW;
            orow = (size_t)b * (cH * cW) + h * cW + w;
        }
        #pragma unroll
        for (int j = 0; j < 4; j++) {
            const int c = colBase + tx * 4 + j;
            float v = acc[i][j] + bias[c];
            if (EPI == 1) {
                v = 0.5f * v * (1.0f + erff(v * 0.70710678118654752f));
            } else if (EPI == 2) {
                v += res[orow * cC + c];
            } else if (EPI == 3) {
                v += res[(size_t)r * Nn + c];
            }
            Cout[orow * (size_t)Nn + c] = v;
        }
    }
}

// ---------------------------------------------------------------------------
// Windowed attention: one block per (window, head).
// qkv row layout: col = which*192 + head*32 + d
// out layout: (win*49+i, head*32+d) within C=192
// ---------------------------------------------------------------------------
__global__ __launch_bounds__(256) void attn_kernel(
    const float* __restrict__ qkv, const float* __restrict__ rpb,
    float* __restrict__ out)
{
    __shared__ float q[49][33], k[49][33], v[49][33];
    __shared__ float s[49][49];

    const int win = blockIdx.x, head = blockIdx.y;
    const int tid = threadIdx.x;
    const size_t base = (size_t)win * cN * (3 * cC) + head * cHD;

    for (int idx = tid; idx < cN * cHD; idx += 256) {
        int i = idx >> 5, d = idx & 31;
        size_t p = base + (size_t)i * (3 * cC) + d;
        q[i][d] = qkv[p];
        k[i][d] = qkv[p + cC];
        v[i][d] = qkv[p + 2 * cC];
    }
    __syncthreads();

    const int wrem = win & 63;
    const int wh = wrem >> 3, ww = wrem & 7;

    for (int idx = tid; idx < cN * cN; idx += 256) {
        int i = idx / cN, j = idx - cN * i;
        float acc = 0.f;
        #pragma unroll
        for (int d = 0; d < cHD; d++) acc += q[i][d] * k[j][d];
        acc *= SCALE;
        const int i1 = i / 7, j1 = i % 7, i2 = j / 7, j2 = j % 7;
        const int ridx = (i1 - i2 + 6) * 13 + (j1 - j2 + 6);
        acc += rpb[ridx * cNH + head];
        // shift mask (region ids in *image* coords; nonzero only for edge windows)
        const int hi = wh * 7 + i1, hj = wh * 7 + i2;
        const int wi = ww * 7 + j1, wj = ww * 7 + j2;
        const int ci = (hi < 49 ? 0 : (hi < 53 ? 3 : 6)) + (wi < 49 ? 0 : (wi < 53 ? 1 : 2));
        const int cj = (hj < 49 ? 0 : (hj < 53 ? 3 : 6)) + (wj < 49 ? 0 : (wj < 53 ? 1 : 2));
        if (ci != cj) acc -= 100.0f;
        s[i][j] = acc;
    }
    __syncthreads();

    if (tid < cN) {
        float mx = -1e30f;
        #pragma unroll
        for (int j = 0; j < cN; j++) mx = fmaxf(mx, s[tid][j]);
        float sum = 0.f;
        #pragma unroll
        for (int j = 0; j < cN; j++) {
            float e = __expf(s[tid][j] - mx);
            s[tid][j] = e;
            sum += e;
        }
        const float rcp = 1.0f / sum;
        #pragma unroll
        for (int j = 0; j < cN; j++) s[tid][j] *= rcp;
    }
    __syncthreads();

    for (int idx = tid; idx < cN * cHD; idx += 256) {
        int i = idx >> 5, d = idx & 31;
        float acc = 0.f;
        #pragma unroll
        for (int j = 0; j < cN; j++) acc += s[i][j] * v[j][d];
        out[((size_t)win * cN + i) * cC + head * cHD + d] = acc;
    }
}

// ---------------------------------------------------------------------------
// Launch
// ---------------------------------------------------------------------------
extern "C" void kernel_launch(void* const* d_in, const int* in_sizes, int n_in,
                              void* d_out, int out_size)
{
    const float* x       = (const float*)d_in[0];
    const float* n1g     = (const float*)d_in[1];
    const float* n1b     = (const float*)d_in[2];
    const float* qkv_w   = (const float*)d_in[3];
    const float* qkv_b   = (const float*)d_in[4];
    const float* rpb     = (const float*)d_in[5];
    const float* proj_w  = (const float*)d_in[6];
    const float* proj_b  = (const float*)d_in[7];
    const float* n2g     = (const float*)d_in[8];
    const float* n2b     = (const float*)d_in[9];
    const float* fc1_w   = (const float*)d_in[10];
    const float* fc1_b   = (const float*)d_in[11];
    const float* fc2_w   = (const float*)d_in[12];
    const float* fc2_b   = (const float*)d_in[13];
    float* out = (float*)d_out;

    float *bufA, *bufB, *bufBig;
    cudaGetSymbolAddress((void**)&bufA,   g_buf_a);
    cudaGetSymbolAddress((void**)&bufB,   g_buf_b);
    cudaGetSymbolAddress((void**)&bufBig, g_buf_big);

    const int MB = ROWS / 128; // 784

    // 1) LN1 + shift + window partition:  x -> bufA (window-ordered rows)
    ln_kernel<true><<<ROWS, 192>>>(x, n1g, n1b, bufA);

    // 2) QKV GEMM: bufA[100352,192] @ qkv_w[192,576] -> bufBig
    sgemm_kernel<0><<<dim3(576 / 64, MB), 256>>>(bufA, qkv_w, qkv_b, nullptr, bufBig, 576, 192);

    // 3) Windowed attention: bufBig -> bufB (window-ordered, heads merged in C)
    attn_kernel<<<dim3(cB * cNW, cNH), 256>>>(bufBig, rpb, bufB);

    // 4) proj GEMM + window reverse + unshift + residual(x): bufB -> bufA (= x1)
    sgemm_kernel<2><<<dim3(192 / 64, MB), 256>>>(bufB, proj_w, proj_b, x, bufA, 192, 192);

    // 5) LN2: bufA -> bufB
    ln_kernel<false><<<ROWS, 192>>>(bufA, n2g, n2b, bufB);

    // 6) fc1 + GELU: bufB[100352,192] @ fc1_w[192,768] -> bufBig
    sgemm_kernel<1><<<dim3(768 / 64, MB), 256>>>(bufB, fc1_w, fc1_b, nullptr, bufBig, 768, 192);

    // 7) fc2 + residual(x1): bufBig[100352,768] @ fc2_w[768,192] + bufA -> out
    sgemm_kernel<3><<<dim3(192 / 64, MB), 256>>>(bufBig, fc2_w, fc2_b, bufA, out, 192, 768);
}

// round 2
// speedup vs baseline: 1.9900x; 1.9900x over previous
#include <cuda_runtime.h>
#include <math.h>
#include <stdint.h>

// ---------------------------------------------------------------------------
// Problem constants
// ---------------------------------------------------------------------------
constexpr int cB  = 32;
constexpr int cH  = 56;
constexpr int cW  = 56;
constexpr int cC  = 192;
constexpr int cSS = 3;
constexpr int cNH = 6;
constexpr int cHD = 32;
constexpr int cN  = 49;
constexpr int cNW = 64;
constexpr int ROWS = cB * cNW * cN;   // 100352
constexpr float SCALE = 0.17677669529663687f;

// ---------------------------------------------------------------------------
// Scratch
// ---------------------------------------------------------------------------
__device__ float g_buf_a[(size_t)ROWS * cC];
__device__ float g_buf_b[(size_t)ROWS * cC];
__device__ float g_buf_big[(size_t)ROWS * 4 * cC];

// ---------------------------------------------------------------------------
// LayerNorm (+ optional shift + window partition gather)
// ---------------------------------------------------------------------------
template <bool SHIFT>
__global__ __launch_bounds__(192) void ln_kernel(
    const float* __restrict__ in, const float* __restrict__ g,
    const float* __restrict__ bb, float* __restrict__ out)
{
    const int r = blockIdx.x;
    size_t src;
    if (SHIFT) {
        int win = r / cN, n = r % cN;
        int b = win >> 6, wrem = win & 63;
        int wh = wrem >> 3, ww = wrem & 7;
        int ii = n / 7, jj = n % 7;
        int h = wh * 7 + ii + cSS; if (h >= cH) h -= cH;
        int w = ww * 7 + jj + cSS; if (w >= cW) w -= cW;
        src = (size_t)b * (cH * cW) + h * cW + w;
    } else {
        src = (size_t)r;
    }
    const int t = threadIdx.x;
    float v = in[src * cC + t];
    float s1 = v, s2 = v * v;
    #pragma unroll
    for (int o = 16; o; o >>= 1) {
        s1 += __shfl_xor_sync(0xffffffffu, s1, o);
        s2 += __shfl_xor_sync(0xffffffffu, s2, o);
    }
    __shared__ float sh1[6], sh2[6];
    const int wid = t >> 5, lane = t & 31;
    if (lane == 0) { sh1[wid] = s1; sh2[wid] = s2; }
    __syncthreads();
    float t1 = 0.f, t2 = 0.f;
    #pragma unroll
    for (int i = 0; i < 6; i++) { t1 += sh1[i]; t2 += sh2[i]; }
    const float mu  = t1 * (1.0f / cC);
    const float var = t2 * (1.0f / cC) - mu * mu;
    const float inv = rsqrtf(var + 1e-5f);
    out[(size_t)r * cC + t] = (v - mu) * inv * g[t] + bb[t];
}

// ---------------------------------------------------------------------------
// tf32 tensor-core GEMM.  C[M,N] = A[M,K] @ B[K,N]  (+ epilogue)
// BM=128 BN=64 BK=16, 4 warps, warp tile 64x32, m16n8k8 tf32 mma,
// cp.async double-buffered smem pipeline.
// EPI 0: +bias        EPI 1: gelu(+bias)
// EPI 2: scatter(window reverse+unshift) + res    EPI 3: +bias + res[row]
// ---------------------------------------------------------------------------
#define CP_ASYNC16(dst_u32, src_ptr) \
    asm volatile("cp.async.cg.shared.global [%0], [%1], 16;\n" :: "r"(dst_u32), "l"(src_ptr))
#define CP_COMMIT() asm volatile("cp.async.commit_group;\n")
#define CP_WAIT(n)  asm volatile("cp.async.wait_group %0;\n" :: "n"(n))

__device__ __forceinline__ void mma_tf32(float c[4], const uint32_t a[4], const uint32_t b[2])
{
    asm volatile(
        "mma.sync.aligned.m16n8k8.row.col.f32.tf32.tf32.f32 "
        "{%0,%1,%2,%3}, {%4,%5,%6,%7}, {%8,%9}, {%0,%1,%2,%3};\n"
        : "+f"(c[0]), "+f"(c[1]), "+f"(c[2]), "+f"(c[3])
        : "r"(a[0]), "r"(a[1]), "r"(a[2]), "r"(a[3]), "r"(b[0]), "r"(b[1]));
}

template <int EPI>
__global__ __launch_bounds__(128) void mma_gemm(
    const float* __restrict__ A, const float* __restrict__ Bm,
    const float* __restrict__ bias, const float* __restrict__ res,
    float* __restrict__ Cout, int Nn, int K)
{
    constexpr int AS_S = 20;   // 16 + 4 pad (80B rows, 16B aligned)
    constexpr int BS_S = 68;   // 64 + 4 pad (272B rows, 16B aligned)
    __shared__ float As[2][128 * AS_S];
    __shared__ float Bs[2][16 * BS_S];

    const int tid  = threadIdx.x;
    const int lane = tid & 31;
    const int warp = tid >> 5;
    const int wm = warp >> 1, wn = warp & 1;
    const int g = lane >> 2, c = lane & 3;
    const int rowBase = blockIdx.y * 128;
    const int colBase = blockIdx.x * 64;

    float acc[4][4][4];
    #pragma unroll
    for (int i = 0; i < 4; i++)
        #pragma unroll
        for (int j = 0; j < 4; j++)
            #pragma unroll
            for (int l = 0; l < 4; l++) acc[i][j][l] = 0.f;

    const int aChunk = tid & 3;          // 16B chunk within k16
    const int aRow0  = tid >> 2;         // 0..31 ; +32*r
    const int S = K / 16;

    // ---- stage loader (macro-ish via lambda) ----
    auto load_stage = [&](int buf, int k0) {
        #pragma unroll
        for (int r = 0; r < 4; r++) {
            const int row = aRow0 + 32 * r;
            const float* src = A + (size_t)(rowBase + row) * K + k0 + aChunk * 4;
            uint32_t dst = (uint32_t)__cvta_generic_to_shared(&As[buf][row * AS_S + aChunk * 4]);
            CP_ASYNC16(dst, src);
        }
        #pragma unroll
        for (int r = 0; r < 2; r++) {
            const int id = tid + r * 128;
            const int k = id >> 4, ch = id & 15;
            const float* src = Bm + (size_t)(k0 + k) * Nn + colBase + ch * 4;
            uint32_t dst = (uint32_t)__cvta_generic_to_shared(&Bs[buf][k * BS_S + ch * 4]);
            CP_ASYNC16(dst, src);
        }
        CP_COMMIT();
    };

    load_stage(0, 0);

    for (int s = 0; s < S; s++) {
        if (s + 1 < S) {
            load_stage((s + 1) & 1, (s + 1) * 16);
            CP_WAIT(1);
        } else {
            CP_WAIT(0);
        }
        __syncthreads();

        const float* as = As[s & 1];
        const float* bs = Bs[s & 1];
        #pragma unroll
        for (int ks = 0; ks < 2; ks++) {
            const int kb = ks * 8;
            uint32_t af[4][4], bf[4][2];
            #pragma unroll
            for (int mt = 0; mt < 4; mt++) {
                const int m0 = wm * 64 + mt * 16;
                af[mt][0] = __float_as_uint(as[(m0 + g    ) * AS_S + kb + c    ]);
                af[mt][1] = __float_as_uint(as[(m0 + g + 8) * AS_S + kb + c    ]);
                af[mt][2] = __float_as_uint(as[(m0 + g    ) * AS_S + kb + c + 4]);
                af[mt][3] = __float_as_uint(as[(m0 + g + 8) * AS_S + kb + c + 4]);
            }
            #pragma unroll
            for (int nt = 0; nt < 4; nt++) {
                const int n0 = wn * 32 + nt * 8 + g;
                bf[nt][0] = __float_as_uint(bs[(kb + c    ) * BS_S + n0]);
                bf[nt][1] = __float_as_uint(bs[(kb + c + 4) * BS_S + n0]);
            }
            #pragma unroll
            for (int mt = 0; mt < 4; mt++)
                #pragma unroll
                for (int nt = 0; nt < 4; nt++)
                    mma_tf32(acc[mt][nt], af[mt], bf[nt]);
        }
        __syncthreads();
    }

    // ---- epilogue ----
    #pragma unroll
    for (int mt = 0; mt < 4; mt++) {
        #pragma unroll
        for (int half = 0; half < 2; half++) {
            const int r = rowBase + wm * 64 + mt * 16 + g + half * 8;
            size_t orow = (size_t)r;
            if (EPI == 2) {
                int win = r / cN, n = r % cN;
                int b = win >> 6, wrem = win & 63;
                int wh = wrem >> 3, ww = wrem & 7;
                int ii = n / 7, jj = n % 7;
                int h = wh * 7 + ii + cSS; if (h >= cH) h -= cH;
                int w = ww * 7 + jj + cSS; if (w >= cW) w -= cW;
                orow = (size_t)b * (cH * cW) + h * cW + w;
            }
            #pragma unroll
            for (int nt = 0; nt < 4; nt++) {
                const int col = colBase + wn * 32 + nt * 8 + 2 * c;
                float v0 = acc[mt][nt][half * 2 + 0] + bias[col];
                float v1 = acc[mt][nt][half * 2 + 1] + bias[col + 1];
                if (EPI == 1) {
                    v0 = 0.5f * v0 * (1.0f + erff(v0 * 0.70710678118654752f));
                    v1 = 0.5f * v1 * (1.0f + erff(v1 * 0.70710678118654752f));
                } else if (EPI == 2) {
                    v0 += res[orow * cC + col];
                    v1 += res[orow * cC + col + 1];
                } else if (EPI == 3) {
                    v0 += res[(size_t)r * Nn + col];
                    v1 += res[(size_t)r * Nn + col + 1];
                }
                float2 o; o.x = v0; o.y = v1;
                *(float2*)&Cout[orow * (size_t)Nn + col] = o;
            }
        }
    }
}

// ---------------------------------------------------------------------------
// Windowed attention: one block per (window, head)
// ---------------------------------------------------------------------------
__global__ __launch_bounds__(256) void attn_kernel(
    const float* __restrict__ qkv, const float* __restrict__ rpb,
    float* __restrict__ out)
{
    __shared__ float q[49][33], k[49][33], v[49][33];
    __shared__ float s[49][49];

    const int win = blockIdx.x, head = blockIdx.y;
    const int tid = threadIdx.x;
    const size_t base = (size_t)win * cN * (3 * cC) + head * cHD;

    for (int idx = tid; idx < cN * cHD; idx += 256) {
        int i = idx >> 5, d = idx & 31;
        size_t p = base + (size_t)i * (3 * cC) + d;
        q[i][d] = qkv[p];
        k[i][d] = qkv[p + cC];
        v[i][d] = qkv[p + 2 * cC];
    }
    __syncthreads();

    const int wrem = win & 63;
    const int wh = wrem >> 3, ww = wrem & 7;

    for (int idx = tid; idx < cN * cN; idx += 256) {
        int i = idx / cN, j = idx - cN * i;
        float acc = 0.f;
        #pragma unroll
        for (int d = 0; d < cHD; d++) acc += q[i][d] * k[j][d];
        acc *= SCALE;
        const int i1 = i / 7, j1 = i % 7, i2 = j / 7, j2 = j % 7;
        const int ridx = (i1 - i2 + 6) * 13 + (j1 - j2 + 6);
        acc += rpb[ridx * cNH + head];
        const int hi = wh * 7 + i1, hj = wh * 7 + i2;
        const int wi = ww * 7 + j1, wj = ww * 7 + j2;
        const int ci = (hi < 49 ? 0 : (hi < 53 ? 3 : 6)) + (wi < 49 ? 0 : (wi < 53 ? 1 : 2));
        const int cj = (hj < 49 ? 0 : (hj < 53 ? 3 : 6)) + (wj < 49 ? 0 : (wj < 53 ? 1 : 2));
        if (ci != cj) acc -= 100.0f;
        s[i][j] = acc;
    }
    __syncthreads();

    if (tid < cN) {
        float mx = -1e30f;
        #pragma unroll
        for (int j = 0; j < cN; j++) mx = fmaxf(mx, s[tid][j]);
        float sum = 0.f;
        #pragma unroll
        for (int j = 0; j < cN; j++) {
            float e = __expf(s[tid][j] - mx);
            s[tid][j] = e;
            sum += e;
        }
        const float rcp = 1.0f / sum;
        #pragma unroll
        for (int j = 0; j < cN; j++) s[tid][j] *= rcp;
    }
    __syncthreads();

    for (int idx = tid; idx < cN * cHD; idx += 256) {
        int i = idx >> 5, d = idx & 31;
        float acc = 0.f;
        #pragma unroll
        for (int j = 0; j < cN; j++) acc += s[i][j] * v[j][d];
        out[((size_t)win * cN + i) * cC + head * cHD + d] = acc;
    }
}

// ---------------------------------------------------------------------------
// Launch
// ---------------------------------------------------------------------------
extern "C" void kernel_launch(void* const* d_in, const int* in_sizes, int n_in,
                              void* d_out, int out_size)
{
    const float* x       = (const float*)d_in[0];
    const float* n1g     = (const float*)d_in[1];
    const float* n1b     = (const float*)d_in[2];
    const float* qkv_w   = (const float*)d_in[3];
    const float* qkv_b   = (const float*)d_in[4];
    const float* rpb     = (const float*)d_in[5];
    const float* proj_w  = (const float*)d_in[6];
    const float* proj_b  = (const float*)d_in[7];
    const float* n2g     = (const float*)d_in[8];
    const float* n2b     = (const float*)d_in[9];
    const float* fc1_w   = (const float*)d_in[10];
    const float* fc1_b   = (const float*)d_in[11];
    const float* fc2_w   = (const float*)d_in[12];
    const float* fc2_b   = (const float*)d_in[13];
    float* out = (float*)d_out;

    float *bufA, *bufB, *bufBig;
    cudaGetSymbolAddress((void**)&bufA,   g_buf_a);
    cudaGetSymbolAddress((void**)&bufB,   g_buf_b);
    cudaGetSymbolAddress((void**)&bufBig, g_buf_big);

    const int MB = ROWS / 128; // 784

    ln_kernel<true><<<ROWS, 192>>>(x, n1g, n1b, bufA);
    mma_gemm<0><<<dim3(576 / 64, MB), 128>>>(bufA, qkv_w, qkv_b, nullptr, bufBig, 576, 192);
    attn_kernel<<<dim3(cB * cNW, cNH), 256>>>(bufBig, rpb, bufB);
    mma_gemm<2><<<dim3(192 / 64, MB), 128>>>(bufB, proj_w, proj_b, x, bufA, 192, 192);
    ln_kernel<false><<<ROWS, 192>>>(bufA, n2g, n2b, bufB);
    mma_gemm<1><<<dim3(768 / 64, MB), 128>>>(bufB, fc1_w, fc1_b, nullptr, bufBig, 768, 192);
    mma_gemm<3><<<dim3(192 / 64, MB), 128>>>(bufBig, fc2_w, fc2_b, bufA, out, 192, 768);
}